// round 16
// baseline (speedup 1.0000x reference)
#include <cuda_runtime.h>
#include <cuda_bf16.h>

#define NN 100000
#define NE 3200000
#define CAP 96                      // per-node bucket capacity (Poisson(32): P(>=96) ~ 1e-18)

// Scratch (static __device__ allocations — zero-init at load; k_l2 re-zeroes
// d_cnt each replay so the graph is replay-clean without a memset launch)
__device__ int   d_cnt[NN];         // in-degree counts / fill cursors (same array!)
__device__ float d_dinv[NN];        // rsqrt(deg+1)
__device__ int   d_csrF[NN * CAP];  // fixed-stride buckets: rows of node c at [c*CAP, c*CAP+cnt)
__device__ float d_xs[NN * 16];     // xs = dinv * x   (pre-scaled features)
__device__ float d_h1s[NN * 32];    // h1s = dinv * relu(layer1)

// ---------------------------------------------------------------------------
// FUSED deg+fill: one atomic pass. p = atomicAdd(cnt[c]) is both the degree
// increment and the bucket cursor. 4 edges per thread via int4.
__global__ void k_fill(const int4* __restrict__ eir4,
                       const int4* __restrict__ eic4, int E4, int n) {
    int e = blockIdx.x * blockDim.x + threadIdx.x;
    if (e >= E4) return;
    int4 r = eir4[e];
    int4 c = eic4[e];
    if ((unsigned)r.x >= (unsigned)n) r.x = 0;
    if ((unsigned)r.y >= (unsigned)n) r.y = 0;
    if ((unsigned)r.z >= (unsigned)n) r.z = 0;
    if ((unsigned)r.w >= (unsigned)n) r.w = 0;
    if ((unsigned)c.x >= (unsigned)n) c.x = 0;
    if ((unsigned)c.y >= (unsigned)n) c.y = 0;
    if ((unsigned)c.z >= (unsigned)n) c.z = 0;
    if ((unsigned)c.w >= (unsigned)n) c.w = 0;
    int p0 = atomicAdd(&d_cnt[c.x], 1);
    int p1 = atomicAdd(&d_cnt[c.y], 1);
    int p2 = atomicAdd(&d_cnt[c.z], 1);
    int p3 = atomicAdd(&d_cnt[c.w], 1);
    if (p0 < CAP) d_csrF[c.x * CAP + p0] = r.x;
    if (p1 < CAP) d_csrF[c.y * CAP + p1] = r.y;
    if (p2 < CAP) d_csrF[c.z * CAP + p2] = r.z;
    if (p3 < CAP) d_csrF[c.w * CAP + p3] = r.w;
}

// node-parallel prep: dinv = rsqrt(cnt+1), xs = dinv * x
__global__ void k_prep(const float4* __restrict__ x4, int n) {
    int i = blockIdx.x * blockDim.x + threadIdx.x;
    if (i >= n) return;
    int c = d_cnt[i];
    float di = rsqrtf((float)c + 1.0f);
    d_dinv[i] = di;
    float4* xs4 = (float4*)(d_xs + (size_t)i * 16);
#pragma unroll
    for (int j = 0; j < 4; j++) {
        float4 a = x4[(size_t)i * 4 + j];
        xs4[j] = make_float4(di * a.x, di * a.y, di * a.z, di * a.w);
    }
}

// ---------------------------------------------------------------------------
// Fused layer 1: aggregate xs (16 dims, pure sum) + GEMV 16->32 + ReLU,
// writes h1s = dinv * relu(...).
// warp/node; lane = (edge slot s = lane>>2) x (float4 chunk q = lane&3)
// software-pipelined 2 chains -> 16 edges in flight per warp
__global__ void k_l1(const float* __restrict__ W1,
                     const float* __restrict__ b1, int n) {
    __shared__ float sW[16 * 32];
    __shared__ float sb[32];
    int tid = threadIdx.x;
    for (int j = tid; j < 512; j += blockDim.x) sW[j] = W1[j];
    if (tid < 32) sb[tid] = b1[tid];
    __syncthreads();

    int gw = (blockIdx.x * blockDim.x + tid) >> 5;
    int lane = tid & 31;
    if (gw >= n) return;

    int s = lane >> 2;       // 8 edge slots
    int q = lane & 3;        // 4 float4 chunks = 16 dims
    int beg = gw * CAP;
    int cnt = d_cnt[gw]; if (cnt > CAP) cnt = CAP;
    int end = beg + cnt;
    float dc = d_dinv[gw];
    const float4* xs4 = (const float4*)d_xs;

    float4 a0 = make_float4(0.f, 0.f, 0.f, 0.f);
    float4 a1 = make_float4(0.f, 0.f, 0.f, 0.f);
    int i = beg + s;
    for (; i + 8 < end; i += 16) {
        int r0 = d_csrF[i];
        int r1 = d_csrF[i + 8];
        float4 v0 = xs4[(size_t)r0 * 4 + q];
        float4 v1 = xs4[(size_t)r1 * 4 + q];
        a0.x += v0.x; a0.y += v0.y; a0.z += v0.z; a0.w += v0.w;
        a1.x += v1.x; a1.y += v1.y; a1.z += v1.z; a1.w += v1.w;
    }
    if (i < end) {
        int r0 = d_csrF[i];
        float4 v0 = xs4[(size_t)r0 * 4 + q];
        a0.x += v0.x; a0.y += v0.y; a0.z += v0.z; a0.w += v0.w;
    }
    float4 acc = make_float4(a0.x + a1.x, a0.y + a1.y, a0.z + a1.z, a0.w + a1.w);

    // fold edge slots (bits 2,3,4 of lane)
#pragma unroll
    for (int m = 4; m <= 16; m <<= 1) {
        acc.x += __shfl_xor_sync(0xffffffffu, acc.x, m);
        acc.y += __shfl_xor_sync(0xffffffffu, acc.y, m);
        acc.z += __shfl_xor_sync(0xffffffffu, acc.z, m);
        acc.w += __shfl_xor_sync(0xffffffffu, acc.w, m);
    }
    // redistribute: lane d (<16) takes comp d&3 of chunk d>>2
    int src = lane >> 2;
    float c0 = __shfl_sync(0xffffffffu, acc.x, src);
    float c1 = __shfl_sync(0xffffffffu, acc.y, src);
    float c2 = __shfl_sync(0xffffffffu, acc.z, src);
    float c3 = __shfl_sync(0xffffffffu, acc.w, src);
    int cc = lane & 3;
    float agg = (cc == 0) ? c0 : (cc == 1) ? c1 : (cc == 2) ? c2 : c3;

    float v = 0.f;
    if (lane < 16)
        v = dc * (agg + d_xs[(size_t)gw * 16 + lane]);   // + self loop (xs)

    float o = sb[lane];
#pragma unroll
    for (int k = 0; k < 16; k++)
        o += __shfl_sync(0xffffffffu, v, k) * sW[k * 32 + lane];
    d_h1s[(size_t)gw * 32 + lane] = dc * fmaxf(o, 0.f);  // pre-scaled output
}

// Fused layer 2 + MLP tail. warp/node; lane = (slot s = lane>>3) x (chunk q = lane&7)
// software-pipelined 2 chains -> 8 edges in flight per warp.
// Zeroes d_cnt[gw] after use so the next graph replay starts clean.
__global__ void k_l2(const float* __restrict__ W2, const float* __restrict__ b2,
                     const float* __restrict__ Wl1, const float* __restrict__ bl1,
                     const float* __restrict__ Wl4, const float* __restrict__ bl4,
                     float* __restrict__ out, int n) {
    __shared__ float sW2[1024];
    __shared__ float sWl1[1024];
    __shared__ float sb2[32], sbl1[32], sWl4[32];
    int tid = threadIdx.x;
    for (int j = tid; j < 1024; j += blockDim.x) {
        sW2[j] = W2[j];
        sWl1[j] = Wl1[j];
    }
    if (tid < 32) { sb2[tid] = b2[tid]; sbl1[tid] = bl1[tid]; sWl4[tid] = Wl4[tid]; }
    __syncthreads();

    int gw = (blockIdx.x * blockDim.x + tid) >> 5;
    int lane = tid & 31;
    if (gw >= n) return;

    int s = lane >> 3;       // 4 edge slots
    int q = lane & 7;        // 8 float4 chunks = 32 dims
    int beg = gw * CAP;
    int cnt = d_cnt[gw]; if (cnt > CAP) cnt = CAP;
    int end = beg + cnt;
    float dc = d_dinv[gw];
    const float4* h1s4 = (const float4*)d_h1s;

    if (lane == 0) d_cnt[gw] = 0;   // replay-clean (value already consumed)

    float4 a0 = make_float4(0.f, 0.f, 0.f, 0.f);
    float4 a1 = make_float4(0.f, 0.f, 0.f, 0.f);
    int i = beg + s;
    for (; i + 4 < end; i += 8) {
        int r0 = d_csrF[i];
        int r1 = d_csrF[i + 4];
        float4 v0 = h1s4[(size_t)r0 * 8 + q];
        float4 v1 = h1s4[(size_t)r1 * 8 + q];
        a0.x += v0.x; a0.y += v0.y; a0.z += v0.z; a0.w += v0.w;
        a1.x += v1.x; a1.y += v1.y; a1.z += v1.z; a1.w += v1.w;
    }
    if (i < end) {
        int r0 = d_csrF[i];
        float4 v0 = h1s4[(size_t)r0 * 8 + q];
        a0.x += v0.x; a0.y += v0.y; a0.z += v0.z; a0.w += v0.w;
    }
    float4 acc = make_float4(a0.x + a1.x, a0.y + a1.y, a0.z + a1.z, a0.w + a1.w);

    // fold edge slots (bits 3,4)
#pragma unroll
    for (int m = 8; m <= 16; m <<= 1) {
        acc.x += __shfl_xor_sync(0xffffffffu, acc.x, m);
        acc.y += __shfl_xor_sync(0xffffffffu, acc.y, m);
        acc.z += __shfl_xor_sync(0xffffffffu, acc.z, m);
        acc.w += __shfl_xor_sync(0xffffffffu, acc.w, m);
    }
    // lane d takes comp d&3 of chunk d>>2
    int src = lane >> 2;
    float c0 = __shfl_sync(0xffffffffu, acc.x, src);
    float c1 = __shfl_sync(0xffffffffu, acc.y, src);
    float c2 = __shfl_sync(0xffffffffu, acc.z, src);
    float c3 = __shfl_sync(0xffffffffu, acc.w, src);
    int cc = lane & 3;
    float agg = (cc == 0) ? c0 : (cc == 1) ? c1 : (cc == 2) ? c2 : c3;

    float v = dc * (agg + d_h1s[(size_t)gw * 32 + lane]);   // + self loop (h1s)

    float a2 = sb2[lane];
#pragma unroll
    for (int k = 0; k < 32; k++)
        a2 += __shfl_sync(0xffffffffu, v, k) * sW2[k * 32 + lane];
    float h2 = fmaxf(a2, 0.f);

    float a3 = sbl1[lane];
#pragma unroll
    for (int k = 0; k < 32; k++)
        a3 += __shfl_sync(0xffffffffu, h2, k) * sWl1[k * 32 + lane];
    float h3 = fmaxf(a3, 0.f);

    float p = h3 * sWl4[lane];
#pragma unroll
    for (int o = 16; o > 0; o >>= 1) p += __shfl_xor_sync(0xffffffffu, p, o);
    if (lane == 0) out[gw] = p + bl4[0];
}

// ---------------------------------------------------------------------------
extern "C" void kernel_launch(void* const* d_in, const int* in_sizes, int n_in,
                              void* d_out, int out_size) {
    // Runtime input resolution by element count.
    const float* x = 0; const int* ei = 0;
    const float *W1 = 0, *b1 = 0, *W2 = 0, *b2 = 0, *Wl1 = 0, *bl1 = 0, *Wl4 = 0, *bl4 = 0;

    bool alpha = (n_in > 0 && in_sizes[0] == 512);  // alphabetical puts W1 first
    int n1024 = 0, n32 = 0;
    for (int i = 0; i < n_in; i++) {
        int s = in_sizes[i];
        const void* p = d_in[i];
        if (s == 1600000)      x  = (const float*)p;
        else if (s == 6400000) ei = (const int*)p;
        else if (s == 512)     W1 = (const float*)p;
        else if (s == 1)       bl4 = (const float*)p;
        else if (s == 1024) {
            if (n1024 == 0) W2 = (const float*)p; else Wl1 = (const float*)p;
            n1024++;
        } else if (s == 32) {
            if (alpha) {
                if      (n32 == 0) Wl4 = (const float*)p;
                else if (n32 == 1) b1  = (const float*)p;
                else if (n32 == 2) b2  = (const float*)p;
                else               bl1 = (const float*)p;
            } else {
                if      (n32 == 0) b1  = (const float*)p;
                else if (n32 == 1) b2  = (const float*)p;
                else if (n32 == 2) bl1 = (const float*)p;
                else               Wl4 = (const float*)p;
            }
            n32++;
        }
    }
    float* out = (float*)d_out;

    int n = NN;
    int E = NE;
    int E4 = E / 4;

    const int TB = 256;
    int nodeBlocks = (n + TB - 1) / TB;
    int e4Blocks = (E4 + TB - 1) / TB;
    int warpNodeBlocks = (n * 32 + TB - 1) / TB;

    const int4* eir4 = (const int4*)ei;             // rows half
    const int4* eic4 = (const int4*)(ei + E);       // cols half

    k_fill<<<e4Blocks, TB>>>(eir4, eic4, E4, n);
    k_prep<<<nodeBlocks, TB>>>((const float4*)x, n);
    k_l1<<<warpNodeBlocks, TB>>>(W1, b1, n);
    k_l2<<<warpNodeBlocks, TB>>>(W2, b2, Wl1, bl1, Wl4, bl4, out, n);
}

// round 17
// speedup vs baseline: 1.5921x; 1.5921x over previous
#include <cuda_runtime.h>
#include <cuda_bf16.h>

#define NN 100000
#define NE 3200000
#define NBLK ((NN + 255) / 256)   // 391 scan blocks

// Scratch (static __device__ allocations — zero-init at load; scanA re-zeroes
// d_cnt each replay so the graph is replay-clean without a memset launch)
__device__ int   d_cnt[NN];        // in-degree counts (no self loop)
__device__ float d_dinv[NN];       // rsqrt(deg+1)
__device__ int   d_off[NN + 1];    // CSR offsets by col
__device__ int   d_cur[NN];        // fill cursors
__device__ int   d_bsum[NBLK];     // scan block sums
__device__ int   d_csr[NE];        // row ids grouped by col (4B/edge)
__device__ float d_xs[NN * 16];    // xs = dinv * x   (pre-scaled features)
__device__ float d_h1s[NN * 32];   // h1s = dinv * relu(layer1)

// ---------------------------------------------------------------------------
// histogram of col; 4 edges per thread via streaming int4 load
__global__ void k_deg(const int4* __restrict__ eic4, int E4, int n) {
    int e = blockIdx.x * blockDim.x + threadIdx.x;
    if (e >= E4) return;
    int4 c = __ldcs(&eic4[e]);
    if ((unsigned)c.x >= (unsigned)n) c.x = 0;
    if ((unsigned)c.y >= (unsigned)n) c.y = 0;
    if ((unsigned)c.z >= (unsigned)n) c.z = 0;
    if ((unsigned)c.w >= (unsigned)n) c.w = 0;
    atomicAdd(&d_cnt[c.x], 1);
    atomicAdd(&d_cnt[c.y], 1);
    atomicAdd(&d_cnt[c.z], 1);
    atomicAdd(&d_cnt[c.w], 1);
}

// ---- per-block exclusive scan + block sums; zeroes d_cnt for next replay ----
__global__ void k_scanA(int n) {
    __shared__ int ws[8];
    int t = threadIdx.x;
    int i = blockIdx.x * 256 + t;
    int lane = t & 31, w = t >> 5;
    int v = 0;
    if (i < n) {
        v = d_cnt[i];
        d_cnt[i] = 0;                        // replay-clean without memset
    }
    int s = v;
#pragma unroll
    for (int o = 1; o < 32; o <<= 1) {
        int a = __shfl_up_sync(0xffffffffu, s, o);
        if (lane >= o) s += a;
    }
    if (lane == 31) ws[w] = s;
    __syncthreads();
    if (t < 8) {
        int a = ws[t];
#pragma unroll
        for (int o = 1; o < 8; o <<= 1) {
            int b = __shfl_up_sync(0xffu, a, o);
            if (t >= o) a += b;
        }
        ws[t] = a;
    }
    __syncthreads();
    int base = w ? ws[w - 1] : 0;
    int incl = base + s;
    if (i < n) {
        d_off[i] = incl - v;                 // exclusive within block
        d_dinv[i] = rsqrtf((float)v + 1.0f); // fused dinv
    }
    if (t == 255) d_bsum[blockIdx.x] = incl;
}

// finalize offsets (redundant block-sum reduction, smem broadcast) + xs = dinv*x
__global__ void k_scanC(const float4* __restrict__ x4, int n, int E) {
    __shared__ int red[8];
    __shared__ int sbase;
    int t = threadIdx.x;
    int bid = blockIdx.x;
    int lane = t & 31, w = t >> 5;

    int partial = 0;
    for (int j = t; j < bid; j += 256) partial += d_bsum[j];
#pragma unroll
    for (int o = 16; o > 0; o >>= 1)
        partial += __shfl_xor_sync(0xffffffffu, partial, o);
    if (lane == 0) red[w] = partial;
    __syncthreads();
    if (t == 0) {
        int b = 0;
#pragma unroll
        for (int j = 0; j < 8; j++) b += red[j];
        sbase = b;
    }
    __syncthreads();
    int base = sbase;

    int i = bid * 256 + t;
    if (i < n) {
        int o = d_off[i] + base;
        d_off[i] = o;
        d_cur[i] = o;
        float di = d_dinv[i];
        float4* xs4 = (float4*)(d_xs + (size_t)i * 16);
#pragma unroll
        for (int j = 0; j < 4; j++) {
            float4 a = x4[(size_t)i * 4 + j];
            xs4[j] = make_float4(di * a.x, di * a.y, di * a.z, di * a.w);
        }
    }
    if (i == 0) d_off[n] = E;
}

// counting-sort fill, 4 edges per thread; streaming loads + streaming stores
__global__ void k_fill(const int4* __restrict__ eir4,
                       const int4* __restrict__ eic4, int E4, int n) {
    int e = blockIdx.x * blockDim.x + threadIdx.x;
    if (e >= E4) return;
    int4 r = __ldcs(&eir4[e]);
    int4 c = __ldcs(&eic4[e]);
    if ((unsigned)r.x >= (unsigned)n) r.x = 0;
    if ((unsigned)r.y >= (unsigned)n) r.y = 0;
    if ((unsigned)r.z >= (unsigned)n) r.z = 0;
    if ((unsigned)r.w >= (unsigned)n) r.w = 0;
    if ((unsigned)c.x >= (unsigned)n) c.x = 0;
    if ((unsigned)c.y >= (unsigned)n) c.y = 0;
    if ((unsigned)c.z >= (unsigned)n) c.z = 0;
    if ((unsigned)c.w >= (unsigned)n) c.w = 0;
    int p0 = atomicAdd(&d_cur[c.x], 1);
    int p1 = atomicAdd(&d_cur[c.y], 1);
    int p2 = atomicAdd(&d_cur[c.z], 1);
    int p3 = atomicAdd(&d_cur[c.w], 1);
    __stcs(&d_csr[p0], r.x);
    __stcs(&d_csr[p1], r.y);
    __stcs(&d_csr[p2], r.z);
    __stcs(&d_csr[p3], r.w);
}

// ---------------------------------------------------------------------------
// Fused layer 1: aggregate xs (16 dims, pure sum) + GEMV 16->32 + ReLU,
// writes h1s = dinv * relu(...).
// warp/node; lane = (edge slot s = lane>>2) x (float4 chunk q = lane&3)
// software-pipelined 2 chains -> 16 edges in flight per warp
__global__ void k_l1(const float* __restrict__ W1,
                     const float* __restrict__ b1, int n) {
    __shared__ float sW[16 * 32];
    __shared__ float sb[32];
    int tid = threadIdx.x;
    for (int j = tid; j < 512; j += blockDim.x) sW[j] = W1[j];
    if (tid < 32) sb[tid] = b1[tid];
    __syncthreads();

    int gw = (blockIdx.x * blockDim.x + tid) >> 5;
    int lane = tid & 31;
    if (gw >= n) return;

    int s = lane >> 2;       // 8 edge slots
    int q = lane & 3;        // 4 float4 chunks = 16 dims
    int beg = d_off[gw], end = d_off[gw + 1];
    float dc = d_dinv[gw];
    const float4* xs4 = (const float4*)d_xs;

    float4 a0 = make_float4(0.f, 0.f, 0.f, 0.f);
    float4 a1 = make_float4(0.f, 0.f, 0.f, 0.f);
    int i = beg + s;
    for (; i + 8 < end; i += 16) {
        int r0 = __ldcs(&d_csr[i]);
        int r1 = __ldcs(&d_csr[i + 8]);
        float4 v0 = xs4[(size_t)r0 * 4 + q];
        float4 v1 = xs4[(size_t)r1 * 4 + q];
        a0.x += v0.x; a0.y += v0.y; a0.z += v0.z; a0.w += v0.w;
        a1.x += v1.x; a1.y += v1.y; a1.z += v1.z; a1.w += v1.w;
    }
    if (i < end) {
        int r0 = __ldcs(&d_csr[i]);
        float4 v0 = xs4[(size_t)r0 * 4 + q];
        a0.x += v0.x; a0.y += v0.y; a0.z += v0.z; a0.w += v0.w;
    }
    float4 acc = make_float4(a0.x + a1.x, a0.y + a1.y, a0.z + a1.z, a0.w + a1.w);

    // fold edge slots (bits 2,3,4 of lane)
#pragma unroll
    for (int m = 4; m <= 16; m <<= 1) {
        acc.x += __shfl_xor_sync(0xffffffffu, acc.x, m);
        acc.y += __shfl_xor_sync(0xffffffffu, acc.y, m);
        acc.z += __shfl_xor_sync(0xffffffffu, acc.z, m);
        acc.w += __shfl_xor_sync(0xffffffffu, acc.w, m);
    }
    // redistribute: lane d (<16) takes comp d&3 of chunk d>>2
    int src = lane >> 2;
    float c0 = __shfl_sync(0xffffffffu, acc.x, src);
    float c1 = __shfl_sync(0xffffffffu, acc.y, src);
    float c2 = __shfl_sync(0xffffffffu, acc.z, src);
    float c3 = __shfl_sync(0xffffffffu, acc.w, src);
    int cc = lane & 3;
    float agg = (cc == 0) ? c0 : (cc == 1) ? c1 : (cc == 2) ? c2 : c3;

    float v = 0.f;
    if (lane < 16)
        v = dc * (agg + d_xs[(size_t)gw * 16 + lane]);   // + self loop (xs)

    float o = sb[lane];
#pragma unroll
    for (int k = 0; k < 16; k++)
        o += __shfl_sync(0xffffffffu, v, k) * sW[k * 32 + lane];
    d_h1s[(size_t)gw * 32 + lane] = dc * fmaxf(o, 0.f);  // pre-scaled output
}

// Fused layer 2 + MLP tail. warp/node; lane = (slot s = lane>>3) x (chunk q = lane&7)
// software-pipelined 2 chains -> 8 edges in flight per warp
__global__ void k_l2(const float* __restrict__ W2, const float* __restrict__ b2,
                     const float* __restrict__ Wl1, const float* __restrict__ bl1,
                     const float* __restrict__ Wl4, const float* __restrict__ bl4,
                     float* __restrict__ out, int n) {
    __shared__ float sW2[1024];
    __shared__ float sWl1[1024];
    __shared__ float sb2[32], sbl1[32], sWl4[32];
    int tid = threadIdx.x;
    for (int j = tid; j < 1024; j += blockDim.x) {
        sW2[j] = W2[j];
        sWl1[j] = Wl1[j];
    }
    if (tid < 32) { sb2[tid] = b2[tid]; sbl1[tid] = bl1[tid]; sWl4[tid] = Wl4[tid]; }
    __syncthreads();

    int gw = (blockIdx.x * blockDim.x + tid) >> 5;
    int lane = tid & 31;
    if (gw >= n) return;

    int s = lane >> 3;       // 4 edge slots
    int q = lane & 7;        // 8 float4 chunks = 32 dims
    int beg = d_off[gw], end = d_off[gw + 1];
    float dc = d_dinv[gw];
    const float4* h1s4 = (const float4*)d_h1s;

    float4 a0 = make_float4(0.f, 0.f, 0.f, 0.f);
    float4 a1 = make_float4(0.f, 0.f, 0.f, 0.f);
    int i = beg + s;
    for (; i + 4 < end; i += 8) {
        int r0 = __ldcs(&d_csr[i]);
        int r1 = __ldcs(&d_csr[i + 4]);
        float4 v0 = h1s4[(size_t)r0 * 8 + q];
        float4 v1 = h1s4[(size_t)r1 * 8 + q];
        a0.x += v0.x; a0.y += v0.y; a0.z += v0.z; a0.w += v0.w;
        a1.x += v1.x; a1.y += v1.y; a1.z += v1.z; a1.w += v1.w;
    }
    if (i < end) {
        int r0 = __ldcs(&d_csr[i]);
        float4 v0 = h1s4[(size_t)r0 * 8 + q];
        a0.x += v0.x; a0.y += v0.y; a0.z += v0.z; a0.w += v0.w;
    }
    float4 acc = make_float4(a0.x + a1.x, a0.y + a1.y, a0.z + a1.z, a0.w + a1.w);

    // fold edge slots (bits 3,4)
#pragma unroll
    for (int m = 8; m <= 16; m <<= 1) {
        acc.x += __shfl_xor_sync(0xffffffffu, acc.x, m);
        acc.y += __shfl_xor_sync(0xffffffffu, acc.y, m);
        acc.z += __shfl_xor_sync(0xffffffffu, acc.z, m);
        acc.w += __shfl_xor_sync(0xffffffffu, acc.w, m);
    }
    // lane d takes comp d&3 of chunk d>>2
    int src = lane >> 2;
    float c0 = __shfl_sync(0xffffffffu, acc.x, src);
    float c1 = __shfl_sync(0xffffffffu, acc.y, src);
    float c2 = __shfl_sync(0xffffffffu, acc.z, src);
    float c3 = __shfl_sync(0xffffffffu, acc.w, src);
    int cc = lane & 3;
    float agg = (cc == 0) ? c0 : (cc == 1) ? c1 : (cc == 2) ? c2 : c3;

    float v = dc * (agg + d_h1s[(size_t)gw * 32 + lane]);   // + self loop (h1s)

    float a2 = sb2[lane];
#pragma unroll
    for (int k = 0; k < 32; k++)
        a2 += __shfl_sync(0xffffffffu, v, k) * sW2[k * 32 + lane];
    float h2 = fmaxf(a2, 0.f);

    float a3 = sbl1[lane];
#pragma unroll
    for (int k = 0; k < 32; k++)
        a3 += __shfl_sync(0xffffffffu, h2, k) * sWl1[k * 32 + lane];
    float h3 = fmaxf(a3, 0.f);

    float p = h3 * sWl4[lane];
#pragma unroll
    for (int o = 16; o > 0; o >>= 1) p += __shfl_xor_sync(0xffffffffu, p, o);
    if (lane == 0) out[gw] = p + bl4[0];
}

// ---------------------------------------------------------------------------
extern "C" void kernel_launch(void* const* d_in, const int* in_sizes, int n_in,
                              void* d_out, int out_size) {
    // Runtime input resolution by element count.
    const float* x = 0; const int* ei = 0;
    const float *W1 = 0, *b1 = 0, *W2 = 0, *b2 = 0, *Wl1 = 0, *bl1 = 0, *Wl4 = 0, *bl4 = 0;

    bool alpha = (n_in > 0 && in_sizes[0] == 512);  // alphabetical puts W1 first
    int n1024 = 0, n32 = 0;
    for (int i = 0; i < n_in; i++) {
        int s = in_sizes[i];
        const void* p = d_in[i];
        if (s == 1600000)      x  = (const float*)p;
        else if (s == 6400000) ei = (const int*)p;
        else if (s == 512)     W1 = (const float*)p;
        else if (s == 1)       bl4 = (const float*)p;
        else if (s == 1024) {
            if (n1024 == 0) W2 = (const float*)p; else Wl1 = (const float*)p;
            n1024++;
        } else if (s == 32) {
            if (alpha) {
                if      (n32 == 0) Wl4 = (const float*)p;
                else if (n32 == 1) b1  = (const float*)p;
                else if (n32 == 2) b2  = (const float*)p;
                else               bl1 = (const float*)p;
            } else {
                if      (n32 == 0) b1  = (const float*)p;
                else if (n32 == 1) b2  = (const float*)p;
                else if (n32 == 2) bl1 = (const float*)p;
                else               Wl4 = (const float*)p;
            }
            n32++;
        }
    }
    float* out = (float*)d_out;

    int n = NN;
    int E = NE;
    int E4 = E / 4;

    const int TB = 256;
    int nodeBlocks = (n + TB - 1) / TB;
    int e4Blocks = (E4 + TB - 1) / TB;
    int warpNodeBlocks = (n * 32 + TB - 1) / TB;

    const int4* eir4 = (const int4*)ei;             // rows half
    const int4* eic4 = (const int4*)(ei + E);       // cols half

    k_deg<<<e4Blocks, TB>>>(eic4, E4, n);
    k_scanA<<<nodeBlocks, TB>>>(n);
    k_scanC<<<nodeBlocks, TB>>>((const float4*)x, n, E);
    k_fill<<<e4Blocks, TB>>>(eir4, eic4, E4, n);
    k_l1<<<warpNodeBlocks, TB>>>(W1, b1, n);
    k_l2<<<warpNodeBlocks, TB>>>(W2, b2, Wl1, bl1, Wl4, bl4, out, n);
}